// round 9
// baseline (speedup 1.0000x reference)
#include <cuda_runtime.h>
#include <cuda_fp16.h>
#include <cstdint>

static constexpr int E = 64;
static constexpr int IN_DIM = 512;
static constexpr int NCLS = 10;

#define SWZ(o) ((o) ^ (((o) >> 3) & 0x70))

__device__ __forceinline__ uint32_t packh2(float a, float b) {
    __half2 h = __floats2half2_rn(a, b);
    return *reinterpret_cast<uint32_t*>(&h);
}
__device__ __forceinline__ __half2 u2h(uint32_t u) { return *reinterpret_cast<__half2*>(&u); }
__device__ __forceinline__ uint32_t h2u(__half2 h) { return *reinterpret_cast<uint32_t*>(&h); }
__device__ __forceinline__ uint32_t hfma2u(uint32_t a, uint32_t b, uint32_t c) {
    return h2u(__hfma2(u2h(a), u2h(b), u2h(c)));
}
__device__ __forceinline__ uint32_t hmax0(uint32_t a) {
    __half2 z = __half2half2(__ushort_as_half(0));
    return h2u(__hmax2(u2h(a), z));
}
__device__ __forceinline__ float2 h2f2(uint32_t u) { return __half22float2(u2h(u)); }

__device__ __forceinline__ void mma16816_f32(float d[4], const uint32_t a[4],
                                             uint32_t b0, uint32_t b1) {
    asm volatile(
        "mma.sync.aligned.m16n8k16.row.col.f32.f16.f16.f32 "
        "{%0,%1,%2,%3}, {%4,%5,%6,%7}, {%8,%9}, {%0,%1,%2,%3};\n"
        : "+f"(d[0]), "+f"(d[1]), "+f"(d[2]), "+f"(d[3])
        : "r"(a[0]), "r"(a[1]), "r"(a[2]), "r"(a[3]), "r"(b0), "r"(b1));
}
__device__ __forceinline__ void mma16816_f16(uint32_t d[2], const uint32_t a[4],
                                             uint32_t b0, uint32_t b1) {
    asm volatile(
        "mma.sync.aligned.m16n8k16.row.col.f16.f16.f16.f16 "
        "{%0,%1}, {%2,%3,%4,%5}, {%6,%7}, {%0,%1};\n"
        : "+r"(d[0]), "+r"(d[1])
        : "r"(a[0]), "r"(a[1]), "r"(a[2]), "r"(a[3]), "r"(b0), "r"(b1));
}
__device__ __forceinline__ void mma16816_f16_c0(uint32_t d[2], const uint32_t a[4],
                                                uint32_t b0, uint32_t b1) {
    uint32_t zero = 0;
    asm volatile(
        "mma.sync.aligned.m16n8k16.row.col.f16.f16.f16.f16 "
        "{%0,%1}, {%2,%3,%4,%5}, {%6,%7}, {%8,%8};\n"
        : "=r"(d[0]), "=r"(d[1])
        : "r"(a[0]), "r"(a[1]), "r"(a[2]), "r"(a[3]), "r"(b0), "r"(b1), "r"(zero));
}

// ============================================================================
// Device scratch
// ============================================================================
__device__ __align__(16) float g_Wc[E * IN_DIM];        // fp32 W1[:,:64]@W_feat
// MMA-path layouts
__device__ __align__(16) uint2 g_WcF[32 * 8 * 32];
__device__ __align__(16) uint4 g_W1zF4[512];
__device__ __align__(16) uint4 g_W2F4[512];
__device__ __align__(16) uint32_t g_w1tF[8 * 32];
__device__ __align__(16) float2 g_bias1F[8 * 32];
__device__ __align__(16) float g_logit_off[16];
// FMA-path layouts (uint4 = {h2(j0,k0k1), h2(j1,k0k1), h2(j0,k2k3), h2(j1,k2k3)})
__device__ __align__(16) uint4 g_WcQ[8 * 512];          // per 64-col chunk
__device__ __align__(16) uint4 g_W1zQ[512];
__device__ __align__(16) uint4 g_W2Q[512];              // 0.1*W2
__device__ __align__(16) uint32_t g_w1tH2[32];
__device__ __align__(16) float g_bias1V[E];

// ============================================================================
// Prep 1: Wc fp32
// ============================================================================
__global__ void prep1_kernel(const float* __restrict__ W_feat,
                             const float* __restrict__ W1) {
    int idx = blockIdx.x * 256 + threadIdx.x;
    if (idx >= E * IN_DIM) return;
    int j = idx >> 9, k = idx & 511;
    float acc = 0.f;
    #pragma unroll 8
    for (int e = 0; e < E; e++)
        acc = fmaf(W1[j * 129 + e], W_feat[e * IN_DIM + k], acc);
    g_Wc[idx] = acc;
}

// ============================================================================
// Prep 2: all layouts + folded constants
// ============================================================================
__global__ void prep2_kernel(const float* __restrict__ b_feat,
                             const float* __restrict__ W1,
                             const float* __restrict__ b1,
                             const float* __restrict__ W2,
                             const float* __restrict__ b2,
                             const float* __restrict__ class_emb) {
    int idx = blockIdx.x * 256 + threadIdx.x;
    if (idx < 8192) {                                   // WcF frags (from g_Wc)
        int L = idx & 31, j = (idx >> 5) & 7, q = idx >> 8;
        int n = 8 * j + (L >> 2), k0 = 16 * q + 2 * (L & 3);
        const float* w = g_Wc + n * IN_DIM;
        g_WcF[idx] = make_uint2(packh2(w[k0], w[k0 + 1]), packh2(w[k0 + 8], w[k0 + 9]));
    } else if (idx < 8704) {                            // W1zF4
        int f = idx - 8192;
        int L = f & 31, qp = (f >> 5) & 1, j = f >> 6;
        int n = 8 * j + (L >> 2);
        const float* w = W1 + n * 129 + 64;
        int ka = 32 * qp + 2 * (L & 3), kb = ka + 16;
        g_W1zF4[f] = make_uint4(packh2(w[ka], w[ka + 1]), packh2(w[ka + 8], w[ka + 9]),
                                packh2(w[kb], w[kb + 1]), packh2(w[kb + 8], w[kb + 9]));
    } else if (idx < 9216) {                            // W2F4 (0.1*W2)
        int f = idx - 8704;
        int L = f & 31, qp = (f >> 5) & 1, j = f >> 6;
        int n = 8 * j + (L >> 2);
        const float* w = W2 + n * E;
        int ka = 32 * qp + 2 * (L & 3), kb = ka + 16;
        g_W2F4[f] = make_uint4(
            packh2(0.1f * w[ka], 0.1f * w[ka + 1]), packh2(0.1f * w[ka + 8], 0.1f * w[ka + 9]),
            packh2(0.1f * w[kb], 0.1f * w[kb + 1]), packh2(0.1f * w[kb + 8], 0.1f * w[kb + 9]));
    } else if (idx < 9472) {                            // w1tF
        int f = idx - 9216;
        int L = f & 31, j = f >> 5;
        int n0 = 8 * j + 2 * (L & 3);
        g_w1tF[f] = packh2(W1[n0 * 129 + 128], W1[(n0 + 1) * 129 + 128]);
    } else if (idx < 9728) {                            // bias1F
        int f = idx - 9472;
        int L = f & 31, j = f >> 5;
        int n0 = 8 * j + 2 * (L & 3);
        float2 bb;
        float* bp = &bb.x;
        #pragma unroll
        for (int s = 0; s < 2; s++) {
            int n = n0 + s;
            float acc = b1[n];
            for (int e = 0; e < E; e++) {
                acc = fmaf(W1[n * 129 + e], b_feat[e], acc);
                acc = fmaf(W1[n * 129 + 64 + e], b2[e], acc);
            }
            bp[s] = acc;
        }
        g_bias1F[f] = bb;
    } else if (idx < 9744) {                            // logit offsets
        int cls = idx - 9728;
        float acc = 0.f;
        if (cls < NCLS)
            for (int n = 0; n < E; n++) acc = fmaf(b2[n], class_emb[cls * E + n], acc);
        g_logit_off[cls] = acc;
    } else if (idx < 13840) {                           // WcQ (4096 entries)
        int f = idx - 9744;
        int ch = f >> 9, jj = (f >> 4) & 31, kp = f & 15;
        int j0 = 2 * jj, j1 = j0 + 1, k = ch * 64 + 4 * kp;
        const float* a = g_Wc + j0 * IN_DIM + k;
        const float* b = g_Wc + j1 * IN_DIM + k;
        g_WcQ[f] = make_uint4(packh2(a[0], a[1]), packh2(b[0], b[1]),
                              packh2(a[2], a[3]), packh2(b[2], b[3]));
    } else if (idx < 14352) {                           // W1zQ
        int f = idx - 13840;
        int jj = f >> 4, kp = f & 15;
        const float* a = W1 + (2 * jj) * 129 + 64 + 4 * kp;
        const float* b = W1 + (2 * jj + 1) * 129 + 64 + 4 * kp;
        g_W1zQ[f] = make_uint4(packh2(a[0], a[1]), packh2(b[0], b[1]),
                               packh2(a[2], a[3]), packh2(b[2], b[3]));
    } else if (idx < 14864) {                           // W2Q (0.1*)
        int f = idx - 14352;
        int jj = f >> 4, kp = f & 15;
        const float* a = W2 + (2 * jj) * E + 4 * kp;
        const float* b = W2 + (2 * jj + 1) * E + 4 * kp;
        g_W2Q[f] = make_uint4(
            packh2(0.1f * a[0], 0.1f * a[1]), packh2(0.1f * b[0], 0.1f * b[1]),
            packh2(0.1f * a[2], 0.1f * a[3]), packh2(0.1f * b[2], 0.1f * b[3]));
    } else if (idx < 14896) {                           // w1tH2
        int jj = idx - 14864;
        g_w1tH2[jj] = packh2(W1[(2 * jj) * 129 + 128], W1[(2 * jj + 1) * 129 + 128]);
    } else if (idx < 14960) {                           // bias1V
        int n = idx - 14896;
        float acc = b1[n];
        for (int e = 0; e < E; e++) {
            acc = fmaf(W1[n * 129 + e], b_feat[e], acc);
            acc = fmaf(W1[n * 129 + 64 + e], b2[e], acc);
        }
        g_bias1V[n] = acc;
    }
}

// ============================================================================
// FMA-path GEMV: 2 threads/row, per-jj uint4 weights, shfl-combined pairs.
// pf[kk] = full d for own j-half pairs.
// ============================================================================
__device__ __forceinline__ void gemv_pairs(const uint4* __restrict__ W,
                                           const uint32_t zh[16], int h,
                                           uint32_t pf[16]) {
    #pragma unroll
    for (int jj = 0; jj < 32; jj++) {
        __half2 a0 = __half2half2(__ushort_as_half(0));
        __half2 a1 = a0;
        const uint4* wp = W + jj * 16 + h * 8;
        #pragma unroll
        for (int kp = 0; kp < 8; kp++) {
            uint4 w = wp[kp];
            a0 = __hfma2(u2h(zh[2 * kp]),     u2h(w.x), a0);
            a1 = __hfma2(u2h(zh[2 * kp]),     u2h(w.y), a1);
            a0 = __hfma2(u2h(zh[2 * kp + 1]), u2h(w.z), a0);
            a1 = __hfma2(u2h(zh[2 * kp + 1]), u2h(w.w), a1);
        }
        __half2 lo = __halves2half2(__low2half(a0),  __low2half(a1));
        __half2 hi = __halves2half2(__high2half(a0), __high2half(a1));
        __half2 p  = __hadd2(lo, hi);
        uint32_t other = __shfl_xor_sync(0xffffffffu, h2u(p), 16);
        __half2 full = __hadd2(p, u2h(other));
        if ((jj >> 4) == h) pf[jj & 15] = h2u(full);
    }
}

// ============================================================================
// Main kernel: heterogeneous grid. bid < fmaCtas -> FMA CTA (64 rows, HFMA2
// GEMVs); else MMA CTA (R7 path, 4 warps x 16 rows).
// ============================================================================
__global__ __launch_bounds__(128, 3)
void iter_kernel(const float* __restrict__ x,
                 const float* __restrict__ z0,
                 const float* __restrict__ b2,
                 const float* __restrict__ class_emb,
                 const int* __restrict__ Tptr,
                 float* __restrict__ out,
                 int Bn, int fmaCtas, int fmaRows) {
    __shared__ __align__(16) uint4 sA[512];             // 8 KB
    __shared__ __align__(16) uint4 sB[512];             // 8 KB
    __shared__ __align__(16) uint32_t sC[2112];         // 8448 B
    __shared__ float sCE[NCLS * E];
    __shared__ float sOff[16];

    const int tid  = threadIdx.x;
    const int lane = tid & 31;
    const int warp = tid >> 5;
    const int bid  = blockIdx.x;

    int T = Tptr ? Tptr[0] : 40;
    if (T <= 0 || T > 1000000) {
        float tf = __int_as_float(T);
        T = (tf > 0.5f && tf < 1.0e6f) ? (int)tf : 40;
    }
    const float invT = 1.0f / (float)T;

    for (int i = tid; i < NCLS * E; i += 128) sCE[i] = class_emb[i];
    if (tid < 16) sOff[tid] = g_logit_off[tid];

    if (bid < fmaCtas) {
        // ==================== FMA CTA: 64 rows, 2 threads/row ====================
        const int rl  = (warp << 4) + (lane & 15);      // row-local 0..63
        const int h   = lane >> 4;                      // k-half
        const int row0 = bid * 64;
        const int row  = row0 + rl;

        for (int i = tid; i < 512; i += 128) sB[i] = g_W2Q[i];

        // ---- x-GEMM: u = x @ Wc^T + bias1, fp32 accum of fp16 64-blocks ----
        float u[64];
        #pragma unroll
        for (int j = 0; j < 64; j++) u[j] = 0.f;

        for (int ch = 0; ch < 8; ch++) {
            __syncthreads();
            for (int s = tid; s < 1024; s += 128) {     // stage 64x64 fp32->h2
                int r = s >> 4, q = s & 15;
                float4 v = *(const float4*)(x + (size_t)(row0 + r) * IN_DIM + ch * 64 + q * 4);
                sC[r * 33 + q * 2]     = packh2(v.x, v.y);
                sC[r * 33 + q * 2 + 1] = packh2(v.z, v.w);
            }
            for (int s = tid; s < 512; s += 128) sA[s] = g_WcQ[ch * 512 + s];
            __syncthreads();
            if ((ch >> 2) == h) {
                uint32_t xr[32];
                #pragma unroll
                for (int kk = 0; kk < 32; kk++) xr[kk] = sC[rl * 33 + kk];
                #pragma unroll
                for (int jj = 0; jj < 32; jj++) {
                    __half2 a0 = __half2half2(__ushort_as_half(0));
                    __half2 a1 = a0;
                    const uint4* wp = sA + jj * 16;
                    #pragma unroll
                    for (int kp = 0; kp < 16; kp++) {
                        uint4 w = wp[kp];
                        a0 = __hfma2(u2h(xr[2 * kp]),     u2h(w.x), a0);
                        a1 = __hfma2(u2h(xr[2 * kp]),     u2h(w.y), a1);
                        a0 = __hfma2(u2h(xr[2 * kp + 1]), u2h(w.z), a0);
                        a1 = __hfma2(u2h(xr[2 * kp + 1]), u2h(w.w), a1);
                    }
                    float2 f0 = __half22float2(a0), f1 = __half22float2(a1);
                    u[2 * jj]     += f0.x + f0.y;
                    u[2 * jj + 1] += f1.x + f1.y;
                }
            }
        }
        // combine k-halves, fold bias
        #pragma unroll
        for (int j = 0; j < 64; j++)
            u[j] += __shfl_xor_sync(0xffffffffu, u[j], 16);

        uint32_t uh[16], w1tH[16];
        #pragma unroll
        for (int kk = 0; kk < 16; kk++) {
            int j0 = h * 32 + 2 * kk;
            uh[kk]   = packh2(u[j0] + g_bias1V[j0], u[j0 + 1] + g_bias1V[j0 + 1]);
            w1tH[kk] = g_w1tH2[h * 16 + kk];
        }

        // swap sA to W1zQ
        __syncthreads();
        for (int s = tid; s < 512; s += 128) sA[s] = g_W1zQ[s];
        __syncthreads();

        // y0 = z0 - b2 (own half, fp32 master)
        float y[32];
        uint32_t zh[16];
        #pragma unroll
        for (int q = 0; q < 8; q++) {
            float4 v = *(const float4*)(z0 + (size_t)row * E + h * 32 + q * 4);
            float4 b = *(const float4*)(b2 + h * 32 + q * 4);
            y[4 * q]     = v.x - b.x; y[4 * q + 1] = v.y - b.y;
            y[4 * q + 2] = v.z - b.z; y[4 * q + 3] = v.w - b.w;
        }
        #pragma unroll
        for (int kk = 0; kk < 16; kk++) zh[kk] = packh2(y[2 * kk], y[2 * kk + 1]);

        // ---- recurrence ----
        for (int step = 0; step < T; step++) {
            const float tv = (float)step * invT;
            const uint32_t tvu = packh2(tv, tv);
            uint32_t pf[16];
            gemv_pairs(sA, zh, h, pf);                  // y @ W1z^T partial->full
            uint32_t hh[16];
            #pragma unroll
            for (int kk = 0; kk < 16; kk++) {
                uint32_t d = h2u(__hadd2(u2h(pf[kk]),
                                         u2h(hfma2u(tvu, w1tH[kk], uh[kk]))));
                hh[kk] = hmax0(d);
            }
            gemv_pairs(sB, hh, h, pf);                  // h @ (0.1*W2)^T
            #pragma unroll
            for (int kk = 0; kk < 16; kk++) {
                float2 f = h2f2(pf[kk]);
                y[2 * kk]     = fmaf(0.9f, y[2 * kk],     f.x);
                y[2 * kk + 1] = fmaf(0.9f, y[2 * kk + 1], f.y);
                zh[kk] = packh2(y[2 * kk], y[2 * kk + 1]);
            }
        }

        // ---- logits ----
        #pragma unroll 2
        for (int cls = 0; cls < NCLS; cls++) {
            float acc = 0.f;
            const float* ce = &sCE[cls * E + h * 32];
            #pragma unroll
            for (int i = 0; i < 32; i++) acc = fmaf(y[i], ce[i], acc);
            acc += __shfl_xor_sync(0xffffffffu, acc, 16);
            if (h == 0) out[(size_t)row * NCLS + cls] = acc + sOff[cls];
        }
        return;
    }

    // ==================== MMA CTA: R7 path ====================
    const int g  = lane >> 2;
    const int t4 = lane & 3;
    const int rowbase = fmaRows + (bid - fmaCtas) * 64 + warp * 16;
    char* sX  = (char*)sC;
    char* sXw = sX + warp * 2048;

    for (int i = tid; i < 512; i += 128) { sA[i] = g_W1zF4[i]; sB[i] = g_W2F4[i]; }
    __syncthreads();

    uint32_t w1t2[8];
    #pragma unroll
    for (int j = 0; j < 8; j++) w1t2[j] = g_w1tF[j * 32 + lane];

    // u = x @ Wc^T (K=512, fp32 acc)
    float u[8][4];
    #pragma unroll
    for (int j = 0; j < 8; j++)
        #pragma unroll
        for (int c = 0; c < 4; c++) u[j][c] = 0.f;

    for (int ch = 0; ch < 8; ch++) {
        __syncwarp();
        for (int s = lane; s < 128; s += 32) {
            int r = s >> 3, cq = s & 7;
            int rr = rowbase + r; if (rr >= Bn) rr = Bn - 1;
            const float4* p = (const float4*)(x + (size_t)rr * IN_DIM + ch * 64 + cq * 8);
            float4 v0 = p[0], v1 = p[1];
            uint4 pk;
            pk.x = packh2(v0.x, v0.y); pk.y = packh2(v0.z, v0.w);
            pk.z = packh2(v1.x, v1.y); pk.w = packh2(v1.z, v1.w);
            *(uint4*)(sXw + SWZ(r * 128 + cq * 16)) = pk;
        }
        __syncwarp();
        #pragma unroll
        for (int q = 0; q < 4; q++) {
            uint32_t a[4];
            {
                int rb0 = g * 128;
                int rb1 = rb0 + 8 * 128;
                int cb  = q * 32 + t4 * 4;
                a[0] = *(const uint32_t*)(sXw + SWZ(rb0 + cb));
                a[1] = *(const uint32_t*)(sXw + SWZ(rb1 + cb));
                a[2] = *(const uint32_t*)(sXw + SWZ(rb0 + cb + 16));
                a[3] = *(const uint32_t*)(sXw + SWZ(rb1 + cb + 16));
            }
            #pragma unroll
            for (int j = 0; j < 8; j++) {
                uint2 b = g_WcF[((ch * 4 + q) * 8 + j) * 32 + lane];
                mma16816_f32(u[j], a, b.x, b.y);
            }
        }
    }

    uint32_t uh[8][2];
    #pragma unroll
    for (int j = 0; j < 8; j++) {
        float2 bb = g_bias1F[j * 32 + lane];
        uh[j][0] = packh2(u[j][0] + bb.x, u[j][1] + bb.y);
        uh[j][1] = packh2(u[j][2] + bb.x, u[j][3] + bb.y);
    }

    float y[8][4];
    {
        int r0 = rowbase + g; if (r0 >= Bn) r0 = Bn - 1;
        int r1 = r0 + 8;      if (r1 >= Bn) r1 = Bn - 1;
        #pragma unroll
        for (int j = 0; j < 8; j++) {
            float2 bv = *(const float2*)(b2 + 8 * j + 2 * t4);
            float2 v0 = *(const float2*)(z0 + (size_t)r0 * E + 8 * j + 2 * t4);
            float2 v1 = *(const float2*)(z0 + (size_t)r1 * E + 8 * j + 2 * t4);
            y[j][0] = v0.x - bv.x; y[j][1] = v0.y - bv.y;
            y[j][2] = v1.x - bv.x; y[j][3] = v1.y - bv.y;
        }
    }

    for (int step = 0; step < T; step++) {
        const float tv = (float)step * invT;
        const uint32_t tvu = packh2(tv, tv);

        uint32_t a[4][4];
        #pragma unroll
        for (int q = 0; q < 4; q++) {
            a[q][0] = packh2(y[2 * q][0],     y[2 * q][1]);
            a[q][1] = packh2(y[2 * q][2],     y[2 * q][3]);
            a[q][2] = packh2(y[2 * q + 1][0], y[2 * q + 1][1]);
            a[q][3] = packh2(y[2 * q + 1][2], y[2 * q + 1][3]);
        }

        uint32_t dh[8][2];
        #pragma unroll
        for (int j = 0; j < 8; j++) {
            dh[j][0] = hfma2u(tvu, w1t2[j], uh[j][0]);
            dh[j][1] = hfma2u(tvu, w1t2[j], uh[j][1]);
        }
        #pragma unroll
        for (int qp = 0; qp < 2; qp++)
            #pragma unroll
            for (int j = 0; j < 8; j++) {
                uint4 bf = sA[(j * 2 + qp) * 32 + lane];
                mma16816_f16(dh[j], a[2 * qp],     bf.x, bf.y);
                mma16816_f16(dh[j], a[2 * qp + 1], bf.z, bf.w);
            }

        uint32_t ha[4][4];
        #pragma unroll
        for (int q = 0; q < 4; q++) {
            ha[q][0] = hmax0(dh[2 * q][0]);
            ha[q][1] = hmax0(dh[2 * q][1]);
            ha[q][2] = hmax0(dh[2 * q + 1][0]);
            ha[q][3] = hmax0(dh[2 * q + 1][1]);
        }

        uint32_t dl[8][2];
        #pragma unroll
        for (int j = 0; j < 8; j++) {
            uint4 bf0 = sB[(j * 2) * 32 + lane];
            uint4 bf1 = sB[(j * 2 + 1) * 32 + lane];
            mma16816_f16_c0(dl[j], ha[0], bf0.x, bf0.y);
            mma16816_f16(dl[j], ha[1], bf0.z, bf0.w);
            mma16816_f16(dl[j], ha[2], bf1.x, bf1.y);
            mma16816_f16(dl[j], ha[3], bf1.z, bf1.w);
        }

        #pragma unroll
        for (int j = 0; j < 8; j++) {
            float2 lo = h2f2(dl[j][0]);
            float2 hi = h2f2(dl[j][1]);
            y[j][0] = fmaf(0.9f, y[j][0], lo.x);
            y[j][1] = fmaf(0.9f, y[j][1], lo.y);
            y[j][2] = fmaf(0.9f, y[j][2], hi.x);
            y[j][3] = fmaf(0.9f, y[j][3], hi.y);
        }
    }

    #pragma unroll 2
    for (int cls = 0; cls < NCLS; cls++) {
        float acc0 = 0.f, acc1 = 0.f;
        #pragma unroll
        for (int j = 0; j < 8; j++) {
            float2 ce = *(const float2*)(&sCE[cls * E + 8 * j + 2 * t4]);
            acc0 = fmaf(y[j][0], ce.x, fmaf(y[j][1], ce.y, acc0));
            acc1 = fmaf(y[j][2], ce.x, fmaf(y[j][3], ce.y, acc1));
        }
        acc0 += __shfl_xor_sync(0xffffffffu, acc0, 1);
        acc0 += __shfl_xor_sync(0xffffffffu, acc0, 2);
        acc1 += __shfl_xor_sync(0xffffffffu, acc1, 1);
        acc1 += __shfl_xor_sync(0xffffffffu, acc1, 2);
        if (t4 == 0) {
            float off = sOff[cls];
            int r0 = rowbase + g;
            if (r0 < Bn)     out[(size_t)r0 * NCLS + cls] = acc0 + off;
            if (r0 + 8 < Bn) out[(size_t)(r0 + 8) * NCLS + cls] = acc1 + off;
        }
    }
}

// ============================================================================
// Launch
// ============================================================================
extern "C" void kernel_launch(void* const* d_in, const int* in_sizes, int n_in,
                              void* d_out, int out_size) {
    const float* x         = (const float*)d_in[0];
    const float* z0        = (const float*)d_in[1];
    const float* W_feat    = (const float*)d_in[2];
    const float* b_feat    = (const float*)d_in[3];
    const float* W1        = (const float*)d_in[4];
    const float* b1        = (const float*)d_in[5];
    const float* W2        = (const float*)d_in[6];
    const float* b2        = (const float*)d_in[7];
    const float* class_emb = (const float*)d_in[8];
    const int*   T_steps   = (n_in > 9) ? (const int*)d_in[9] : nullptr;
    float* out = (float*)d_out;

    int Bn = in_sizes[1] / E;

    prep1_kernel<<<(E * IN_DIM + 255) / 256, 256>>>(W_feat, W1);
    prep2_kernel<<<(14960 + 255) / 256, 256>>>(b_feat, W1, b1, W2, b2, class_emb);

    int fmaCtas = 0, fmaRows = 0;
    if (Bn >= 32768) { fmaCtas = 148; fmaRows = 148 * 64; }
    int nMma = (Bn - fmaRows + 63) / 64;
    iter_kernel<<<fmaCtas + nMma, 128>>>(x, z0, b2, class_emb, T_steps, out,
                                         Bn, fmaCtas, fmaRows);
}

// round 10
// speedup vs baseline: 2.2202x; 2.2202x over previous
#include <cuda_runtime.h>
#include <cuda_fp16.h>
#include <cstdint>

// ============================================================================
// Portable tensor-core path: mma.sync.m16n8k16 (f16 in, f32 accum).
// The harness compiles for plain sm_100 (no 'a' suffix) -> no tcgen05.
//
// This is the proven-best iter kernel (166.8us, rel_err 2.05e-4) with a
// faster prep prologue (4-way K-split prep1).
// ============================================================================

static constexpr int E = 64;
static constexpr int IN_DIM = 512;
static constexpr int NCLS = 10;

#define SWZ(o) ((o) ^ (((o) >> 3) & 0x70))

__device__ __forceinline__ uint32_t packh2(float a, float b) {
    __half2 h = __floats2half2_rn(a, b);
    return *reinterpret_cast<uint32_t*>(&h);
}

__device__ __forceinline__ void mma16816(float d[4], const uint32_t a[4], uint2 b) {
    asm volatile(
        "mma.sync.aligned.m16n8k16.row.col.f32.f16.f16.f32 "
        "{%0,%1,%2,%3}, {%4,%5,%6,%7}, {%8,%9}, {%0,%1,%2,%3};\n"
        : "+f"(d[0]), "+f"(d[1]), "+f"(d[2]), "+f"(d[3])
        : "r"(a[0]), "r"(a[1]), "r"(a[2]), "r"(a[3]), "r"(b.x), "r"(b.y));
}

// ============================================================================
// Device scratch (no dynamic allocation allowed)
// ============================================================================
__device__ __align__(16) float g_WcP[4 * E * IN_DIM];   // 4-way e-split partials
__device__ __align__(16) uint2 g_W1zF[8 * 4 * 32];      // B-frags of W1[:, 64:128]
__device__ __align__(16) uint2 g_W2F[8 * 4 * 32];       // B-frags of 0.1*W2
__device__ __align__(16) uint2 g_WcF[32 * 8 * 32];      // B-frags of Wc (K=512)
__device__ __align__(16) float g_bias1[E];              // b1 + W1[:, :64] @ b_feat
__device__ __align__(16) float g_w1t[E];                // W1[:, 128]

// ============================================================================
// Prep 1: 4-way e-split partials of Wc = W1[:, :64] @ W_feat  (fast: 131K thr)
// ============================================================================
__global__ void prep1_kernel(const float* __restrict__ W_feat,
                             const float* __restrict__ W1) {
    int idx = blockIdx.x * 256 + threadIdx.x;           // 131072 threads
    if (idx >= 4 * E * IN_DIM) return;
    int p = idx >> 15;
    int r = idx & 32767;
    int j = r >> 9, k = r & 511;
    int e0 = p * 16;
    float acc = 0.f;
    #pragma unroll
    for (int e = 0; e < 16; e++)
        acc = fmaf(W1[j * 129 + e0 + e], W_feat[(e0 + e) * IN_DIM + k], acc);
    g_WcP[idx] = acc;
}

// ============================================================================
// Prep 2: build per-lane B fragments + folded biases (R2 layouts).
// B frag for m16n8k16.col: lane L (g=L>>2, t=L&3), n-tile j, k-chunk q:
//   b0 = {W[8j+g][16q+2t],   W[8j+g][16q+2t+1]}
//   b1 = {W[8j+g][16q+2t+8], W[8j+g][16q+2t+9]}
// ============================================================================
__global__ void prep2_kernel(const float* __restrict__ b_feat,
                             const float* __restrict__ W1,
                             const float* __restrict__ b1,
                             const float* __restrict__ W2) {
    int idx = blockIdx.x * 256 + threadIdx.x;
    if (idx < 8192) {                                   // WcF from partial sums
        int L = idx & 31, j = (idx >> 5) & 7, q = idx >> 8;
        int n = 8 * j + (L >> 2), k0 = 16 * q + 2 * (L & 3);
        float w[4];
        #pragma unroll
        for (int s = 0; s < 4; s++) {
            int k = k0 + (s & 1) + (s >> 1) * 8;        // k0, k0+1, k0+8, k0+9
            float acc = 0.f;
            #pragma unroll
            for (int p = 0; p < 4; p++) acc += g_WcP[p * 32768 + n * IN_DIM + k];
            w[s] = acc;
        }
        g_WcF[idx] = make_uint2(packh2(w[0], w[1]), packh2(w[2], w[3]));
    } else if (idx < 9216) {                            // W1zF
        int f = idx - 8192;
        int L = f & 31, q = (f >> 5) & 3, j = f >> 7;
        int n = 8 * j + (L >> 2), k0 = 16 * q + 2 * (L & 3);
        const float* w = W1 + n * 129 + 64;
        g_W1zF[f] = make_uint2(packh2(w[k0], w[k0 + 1]),
                               packh2(w[k0 + 8], w[k0 + 9]));
    } else if (idx < 10240) {                           // W2F (pre-scaled by 0.1)
        int f = idx - 9216;
        int L = f & 31, q = (f >> 5) & 3, j = f >> 7;
        int n = 8 * j + (L >> 2), k0 = 16 * q + 2 * (L & 3);
        const float* w = W2 + n * E;
        g_W2F[f] = make_uint2(packh2(0.1f * w[k0], 0.1f * w[k0 + 1]),
                              packh2(0.1f * w[k0 + 8], 0.1f * w[k0 + 9]));
    } else if (idx < 10240 + E) {                       // bias1, w1t
        int n = idx - 10240;
        float acc = b1[n];
        for (int e = 0; e < E; e++) acc += W1[n * 129 + e] * b_feat[e];
        g_bias1[n] = acc;
        g_w1t[n] = W1[n * 129 + 128];
    }
}

// ============================================================================
// Main kernel: 128 threads = 4 warps, 32 rows/warp. Register-resident
// recurrence, no in-loop synchronization of any kind. (Proven 166.8us.)
// ============================================================================
__global__ __launch_bounds__(128, 2)
void iter_kernel(const float* __restrict__ x,
                 const float* __restrict__ z0,
                 const float* __restrict__ b2,
                 const float* __restrict__ class_emb,
                 const int* __restrict__ Tptr,
                 float* __restrict__ out,
                 int Bn) {
    __shared__ __align__(16) uint2 sW1z[1024];          // 8 KB
    __shared__ __align__(16) uint2 sW2[1024];           // 8 KB
    __shared__ float sBias1[E], sW1t[E], sB2s[E];
    __shared__ float sCE[NCLS * E];
    __shared__ __align__(128) char sX[128 * 128];       // 16 KB fp16, swizzled

    const int tid  = threadIdx.x;
    const int lane = tid & 31;
    const int g    = lane >> 2;
    const int t4   = lane & 3;
    const int warp = tid >> 5;
    const int ctabase = blockIdx.x * 128;
    const int rowbase = ctabase + warp * 32;

    // ---- cooperative weight/constant loads ----
    for (int i = tid; i < 1024; i += 128) { sW1z[i] = g_W1zF[i]; sW2[i] = g_W2F[i]; }
    if (tid < E) {
        sBias1[tid] = g_bias1[tid];
        sW1t[tid]   = g_w1t[tid];
        sB2s[tid]   = 0.1f * b2[tid];
    }
    for (int i = tid; i < NCLS * E; i += 128) sCE[i] = class_emb[i];

    // ======================= u = x @ Wc^T  (K = 512) =======================
    float u[2][8][4];
    #pragma unroll
    for (int i = 0; i < 2; i++)
        #pragma unroll
        for (int j = 0; j < 8; j++)
            #pragma unroll
            for (int c = 0; c < 4; c++) u[i][j][c] = 0.f;

    for (int ch = 0; ch < 8; ch++) {
        __syncthreads();   // protect sX reuse (also covers initial weight loads)
        // stage 128 rows x 64 cols fp32 -> fp16, swizzled
        for (int s = tid; s < 1024; s += 128) {
            int r = s >> 3, cq = s & 7;
            int rr = ctabase + r; if (rr >= Bn) rr = Bn - 1;
            const float4* p = (const float4*)(x + (size_t)rr * IN_DIM + ch * 64 + cq * 8);
            float4 v0 = p[0], v1 = p[1];
            uint4 pk;
            pk.x = packh2(v0.x, v0.y); pk.y = packh2(v0.z, v0.w);
            pk.z = packh2(v1.x, v1.y); pk.w = packh2(v1.z, v1.w);
            *(uint4*)(sX + SWZ(r * 128 + cq * 16)) = pk;
        }
        __syncthreads();
        #pragma unroll
        for (int q = 0; q < 4; q++) {
            uint32_t a[2][4];
            #pragma unroll
            for (int i = 0; i < 2; i++) {
                int rb0 = (warp * 32 + i * 16 + g) * 128;
                int rb1 = rb0 + 8 * 128;
                int cb  = q * 32 + t4 * 4;
                a[i][0] = *(const uint32_t*)(sX + SWZ(rb0 + cb));
                a[i][1] = *(const uint32_t*)(sX + SWZ(rb1 + cb));
                a[i][2] = *(const uint32_t*)(sX + SWZ(rb0 + cb + 16));
                a[i][3] = *(const uint32_t*)(sX + SWZ(rb1 + cb + 16));
            }
            #pragma unroll
            for (int j = 0; j < 8; j++) {
                uint2 b = g_WcF[((ch * 4 + q) * 8 + j) * 32 + lane];
                mma16816(u[0][j], a[0], b);
                mma16816(u[1][j], a[1], b);
            }
        }
    }
    __syncthreads();

    // ---- fold bias1 into u, compress to half2 (frees 32 regs) ----
    uint32_t uh[2][8][2];
    #pragma unroll
    for (int j = 0; j < 8; j++) {
        float b0 = sBias1[8 * j + 2 * t4], b1v = sBias1[8 * j + 2 * t4 + 1];
        #pragma unroll
        for (int i = 0; i < 2; i++) {
            uh[i][j][0] = packh2(u[i][j][0] + b0, u[i][j][1] + b1v);
            uh[i][j][1] = packh2(u[i][j][2] + b0, u[i][j][3] + b1v);
        }
    }

    float w1tv[8][2], b2v[8][2];
    #pragma unroll
    for (int j = 0; j < 8; j++) {
        w1tv[j][0] = sW1t[8 * j + 2 * t4];  w1tv[j][1] = sW1t[8 * j + 2 * t4 + 1];
        b2v[j][0]  = sB2s[8 * j + 2 * t4];  b2v[j][1]  = sB2s[8 * j + 2 * t4 + 1];
    }

    // ---- z0 -> registers (D-fragment layout, fp32 master) ----
    float z[2][8][4];
    #pragma unroll
    for (int i = 0; i < 2; i++) {
        int r0 = rowbase + i * 16 + g; if (r0 >= Bn) r0 = Bn - 1;
        int r1 = r0 + 8;               if (r1 >= Bn) r1 = Bn - 1;
        #pragma unroll
        for (int j = 0; j < 8; j++) {
            float2 v0 = *(const float2*)(z0 + (size_t)r0 * E + 8 * j + 2 * t4);
            float2 v1 = *(const float2*)(z0 + (size_t)r1 * E + 8 * j + 2 * t4);
            z[i][j][0] = v0.x; z[i][j][1] = v0.y;
            z[i][j][2] = v1.x; z[i][j][3] = v1.y;
        }
    }

    // ---- T ----
    int T = Tptr ? Tptr[0] : 40;
    if (T <= 0 || T > 1000000) {
        float tf = __int_as_float(T);
        T = (tf > 0.5f && tf < 1.0e6f) ? (int)tf : 40;
    }
    const float invT = 1.0f / (float)T;

    // ======================= 40-step recurrence (registers only) ============
    for (int step = 0; step < T; step++) {
        const float tv = (float)step * invT;

        // ---- GEMM1: d = u + t*w1t + z @ W1z^T ----
        float d[2][8][4];
        #pragma unroll
        for (int i = 0; i < 2; i++)
            #pragma unroll
            for (int j = 0; j < 8; j++) {
                float2 lo = __half22float2(*reinterpret_cast<__half2*>(&uh[i][j][0]));
                float2 hi = __half22float2(*reinterpret_cast<__half2*>(&uh[i][j][1]));
                d[i][j][0] = fmaf(tv, w1tv[j][0], lo.x);
                d[i][j][1] = fmaf(tv, w1tv[j][1], lo.y);
                d[i][j][2] = fmaf(tv, w1tv[j][0], hi.x);
                d[i][j][3] = fmaf(tv, w1tv[j][1], hi.y);
            }
        #pragma unroll
        for (int q = 0; q < 4; q++) {
            uint32_t a[2][4];
            #pragma unroll
            for (int i = 0; i < 2; i++) {
                a[i][0] = packh2(z[i][2 * q][0],     z[i][2 * q][1]);
                a[i][1] = packh2(z[i][2 * q][2],     z[i][2 * q][3]);
                a[i][2] = packh2(z[i][2 * q + 1][0], z[i][2 * q + 1][1]);
                a[i][3] = packh2(z[i][2 * q + 1][2], z[i][2 * q + 1][3]);
            }
            #pragma unroll
            for (int j = 0; j < 8; j++) {
                uint2 b = sW1z[(j * 4 + q) * 32 + lane];
                mma16816(d[0][j], a[0], b);
                mma16816(d[1][j], a[1], b);
            }
        }

        // ---- h = relu(d), packed directly as A-fragments ----
        uint32_t ha[2][4][4];
        #pragma unroll
        for (int i = 0; i < 2; i++)
            #pragma unroll
            for (int q = 0; q < 4; q++) {
                ha[i][q][0] = packh2(fmaxf(d[i][2 * q][0], 0.f),     fmaxf(d[i][2 * q][1], 0.f));
                ha[i][q][1] = packh2(fmaxf(d[i][2 * q][2], 0.f),     fmaxf(d[i][2 * q][3], 0.f));
                ha[i][q][2] = packh2(fmaxf(d[i][2 * q + 1][0], 0.f), fmaxf(d[i][2 * q + 1][1], 0.f));
                ha[i][q][3] = packh2(fmaxf(d[i][2 * q + 1][2], 0.f), fmaxf(d[i][2 * q + 1][3], 0.f));
            }

        // ---- GEMM2: z = 0.9*z + 0.1*b2 + h @ (0.1*W2)^T  (z IS the accumulator)
        #pragma unroll
        for (int i = 0; i < 2; i++)
            #pragma unroll
            for (int j = 0; j < 8; j++) {
                z[i][j][0] = fmaf(0.9f, z[i][j][0], b2v[j][0]);
                z[i][j][1] = fmaf(0.9f, z[i][j][1], b2v[j][1]);
                z[i][j][2] = fmaf(0.9f, z[i][j][2], b2v[j][0]);
                z[i][j][3] = fmaf(0.9f, z[i][j][3], b2v[j][1]);
            }
        #pragma unroll
        for (int q = 0; q < 4; q++)
            #pragma unroll
            for (int j = 0; j < 8; j++) {
                uint2 b = sW2[(j * 4 + q) * 32 + lane];
                mma16816(z[0][j], ha[0][q], b);
                mma16816(z[1][j], ha[1][q], b);
            }
    }

    // ======================= logits = z @ class_emb^T =======================
    #pragma unroll 2
    for (int cls = 0; cls < NCLS; cls++) {
        float acc0 = 0.f, acc1 = 0.f, acc2 = 0.f, acc3 = 0.f;
        #pragma unroll
        for (int j = 0; j < 8; j++) {
            float2 ce = *(const float2*)(&sCE[cls * E + 8 * j + 2 * t4]);
            acc0 = fmaf(z[0][j][0], ce.x, fmaf(z[0][j][1], ce.y, acc0));
            acc1 = fmaf(z[0][j][2], ce.x, fmaf(z[0][j][3], ce.y, acc1));
            acc2 = fmaf(z[1][j][0], ce.x, fmaf(z[1][j][1], ce.y, acc2));
            acc3 = fmaf(z[1][j][2], ce.x, fmaf(z[1][j][3], ce.y, acc3));
        }
        acc0 += __shfl_xor_sync(0xffffffffu, acc0, 1);
        acc0 += __shfl_xor_sync(0xffffffffu, acc0, 2);
        acc1 += __shfl_xor_sync(0xffffffffu, acc1, 1);
        acc1 += __shfl_xor_sync(0xffffffffu, acc1, 2);
        acc2 += __shfl_xor_sync(0xffffffffu, acc2, 1);
        acc2 += __shfl_xor_sync(0xffffffffu, acc2, 2);
        acc3 += __shfl_xor_sync(0xffffffffu, acc3, 1);
        acc3 += __shfl_xor_sync(0xffffffffu, acc3, 2);
        if (t4 == 0) {
            int r0 = rowbase + g;
            if (r0 < Bn)      out[(size_t)r0 * NCLS + cls] = acc0;
            if (r0 + 8 < Bn)  out[(size_t)(r0 + 8) * NCLS + cls] = acc1;
            if (r0 + 16 < Bn) out[(size_t)(r0 + 16) * NCLS + cls] = acc2;
            if (r0 + 24 < Bn) out[(size_t)(r0 + 24) * NCLS + cls] = acc3;
        }
    }
}

// ============================================================================
// Launch
// ============================================================================
extern "C" void kernel_launch(void* const* d_in, const int* in_sizes, int n_in,
                              void* d_out, int out_size) {
    const float* x         = (const float*)d_in[0];
    const float* z0        = (const float*)d_in[1];
    const float* W_feat    = (const float*)d_in[2];
    const float* b_feat    = (const float*)d_in[3];
    const float* W1        = (const float*)d_in[4];
    const float* b1        = (const float*)d_in[5];
    const float* W2        = (const float*)d_in[6];
    const float* b2        = (const float*)d_in[7];
    const float* class_emb = (const float*)d_in[8];
    const int*   T_steps   = (n_in > 9) ? (const int*)d_in[9] : nullptr;
    float* out = (float*)d_out;

    int Bn = in_sizes[1] / E;   // z0 is [B, 64]

    prep1_kernel<<<512, 256>>>(W_feat, W1);
    prep2_kernel<<<(10240 + E + 255) / 256, 256>>>(b_feat, W1, b1, W2);

    int grid = (Bn + 127) / 128;
    iter_kernel<<<grid, 128>>>(x, z0, b2, class_emb, T_steps, out, Bn);
}